// round 2
// baseline (speedup 1.0000x reference)
#include <cuda_runtime.h>
#include <cuda_bf16.h>
#include <cstdint>

// ---------------- problem constants ----------------
#define FH_    16
#define FW_    44
#define HW_    704          // FH*FW
#define NCAM   6
#define CIN    512
#define DB     41           // depth bins
#define CT     128          // context channels
#define NO     169          // DB + CT
#define NPIX   4224         // NCAM * HW_
#define NPTS   173184       // NPIX * DB
#define NVOX   16384        // 128*128

// GEMM tiling
#define BM 64
#define BN 64
#define BK 16
#define KSLICES 2
#define KSLICE (CIN / KSLICES)   // 256
#define NSTAGES (KSLICE / BK)    // 16

// ---------------- scratch (__device__ globals) ----------------
__device__ float d_invpost[NCAM * 9];
__device__ float d_combine[NCAM * 9];
__device__ float d_featp[KSLICES * NO * NPIX];  // featT[ks][o][pix]
__device__ float d_dep[NPTS];                   // dep[pix*DB + d]
__device__ float d_cfeat[NPIX * CT];            // cfeat[pix*CT + c]
__device__ int   d_cnt[NVOX];
__device__ int   d_offs[NVOX];
__device__ int   d_rank[NPTS];
__device__ int2  d_sorted[NPTS];                // (pix, depth-as-bits)

// ---------------- f32x2 helpers ----------------
__device__ __forceinline__ unsigned long long pk2(float lo, float hi) {
    unsigned long long r;
    asm("mov.b64 %0, {%1,%2};" : "=l"(r) : "f"(lo), "f"(hi));
    return r;
}
__device__ __forceinline__ void fma2(unsigned long long& d,
                                     unsigned long long a, unsigned long long b) {
    asm("fma.rn.f32x2 %0, %1, %2, %0;" : "+l"(d) : "l"(a), "l"(b));
}
__device__ __forceinline__ float2 upk2(unsigned long long v) {
    float2 r;
    asm("mov.b64 {%0,%1}, %2;" : "=f"(r.x), "=f"(r.y) : "l"(v));
    return r;
}

// ---------------- 3x3 inverse ----------------
__device__ __forceinline__ void inv3(const float* m, float* o) {
    float a=m[0],b=m[1],c=m[2],d=m[3],e=m[4],f=m[5],g=m[6],h=m[7],i=m[8];
    float A  =  (e*i - f*h);
    float Bc = -(d*i - f*g);
    float Cc =  (d*h - e*g);
    float det = a*A + b*Bc + c*Cc;
    float inv = 1.0f / det;
    o[0] = A  * inv;           o[1] = -(b*i - c*h) * inv;  o[2] =  (b*f - c*e) * inv;
    o[3] = Bc * inv;           o[4] =  (a*i - c*g) * inv;  o[5] = -(a*f - c*d) * inv;
    o[6] = Cc * inv;           o[7] = -(a*h - b*g) * inv;  o[8] =  (a*e - b*d) * inv;
}

// ---------------- K0: zero histogram + per-camera matrices ----------------
__global__ void k_init(const float* __restrict__ rots,
                       const float* __restrict__ intrins,
                       const float* __restrict__ post_rots) {
    int b = blockIdx.x;
    if (b < 64) {
        d_cnt[b * 256 + threadIdx.x] = 0;
    } else {
        int n = threadIdx.x;
        if (n >= NCAM) return;
        float ip[9], ii[9];
        inv3(post_rots + n * 9, ip);
        inv3(intrins  + n * 9, ii);
#pragma unroll
        for (int k = 0; k < 9; k++) d_invpost[n * 9 + k] = ip[k];
        const float* R = rots + n * 9;
#pragma unroll
        for (int i = 0; i < 3; i++)
#pragma unroll
            for (int j = 0; j < 3; j++) {
                float s = 0.f;
#pragma unroll
                for (int k = 0; k < 3; k++) s += R[i * 3 + k] * ii[k * 3 + j];
                d_combine[n * 9 + i * 3 + j] = s;
            }
    }
}

// ---------------- GEMM: featT[ks][o][pix] = w[o,:] . x[:,pix] (split-K) ----------------
// grid (66, 3, 2), 128 threads. FFMA2 inner loop, 4 chans x 8 px per thread.
__global__ __launch_bounds__(128) void k_gemm(const float* __restrict__ x,
                                              const float* __restrict__ w) {
    __shared__ float ws[BK][BM];   // [k][m]
    __shared__ float xs[BK][BN];   // [k][n]

    int t    = threadIdx.x;
    int pix0 = blockIdx.x * BN;            // BN divides HW_ -> tile within one camera
    int m0   = blockIdx.y * BM;
    int k0   = blockIdx.z * KSLICE;

    int cam = pix0 / HW_;
    int hw0 = pix0 % HW_;
    const float* xb = x + (size_t)cam * CIN * HW_ + hw0;

    // loader mapping
    int wm = t >> 1;            // 0..63 : W row (channel)
    int wh = t & 1;             // which k-half (8 floats)
    bool wvalid = (m0 + wm) < NO;
    const float* wrow = w + (size_t)(m0 + wm) * CIN + k0 + wh * 8;
    int xk = t >> 3;            // 0..15 : X row (k)
    int xn = (t & 7) * 8;       // 0..56 : X col base
    const float* xrow = xb + (size_t)(k0 + xk) * HW_ + xn;

    // compute mapping
    int ty = t >> 3;            // 0..15 -> chans ty*4
    int tx = t & 7;             // 0..7  -> px tx*8

    float4 wA, wB, xA, xB;
    const float4 Z4 = make_float4(0.f, 0.f, 0.f, 0.f);

    // prefetch stage 0
    {
        wA = wvalid ? *(const float4*)(wrow + 0) : Z4;
        wB = wvalid ? *(const float4*)(wrow + 4) : Z4;
        xA = *(const float4*)(xrow + 0);
        xB = *(const float4*)(xrow + 4);
    }

    unsigned long long acc[4][4];
#pragma unroll
    for (int c = 0; c < 4; c++)
#pragma unroll
        for (int j = 0; j < 4; j++) acc[c][j] = 0ull;

    for (int s = 0; s < NSTAGES; s++) {
        // store staged regs to smem
        ws[wh * 8 + 0][wm] = wA.x; ws[wh * 8 + 1][wm] = wA.y;
        ws[wh * 8 + 2][wm] = wA.z; ws[wh * 8 + 3][wm] = wA.w;
        ws[wh * 8 + 4][wm] = wB.x; ws[wh * 8 + 5][wm] = wB.y;
        ws[wh * 8 + 6][wm] = wB.z; ws[wh * 8 + 7][wm] = wB.w;
        *(float4*)&xs[xk][xn + 0] = xA;
        *(float4*)&xs[xk][xn + 4] = xB;
        __syncthreads();

        if (s + 1 < NSTAGES) {
            int kk = (s + 1) * BK;
            wA = wvalid ? *(const float4*)(wrow + kk + 0) : Z4;
            wB = wvalid ? *(const float4*)(wrow + kk + 4) : Z4;
            xA = *(const float4*)(xrow + (size_t)kk * HW_ + 0);
            xB = *(const float4*)(xrow + (size_t)kk * HW_ + 4);
        }

#pragma unroll
        for (int kk = 0; kk < BK; kk++) {
            float4 a  = *(const float4*)&ws[kk][ty * 4];
            float4 b0 = *(const float4*)&xs[kk][tx * 8];
            float4 b1 = *(const float4*)&xs[kk][tx * 8 + 4];
            unsigned long long p0 = pk2(b0.x, b0.y);
            unsigned long long p1 = pk2(b0.z, b0.w);
            unsigned long long p2 = pk2(b1.x, b1.y);
            unsigned long long p3 = pk2(b1.z, b1.w);
            unsigned long long a0 = pk2(a.x, a.x);
            unsigned long long a1 = pk2(a.y, a.y);
            unsigned long long a2 = pk2(a.z, a.z);
            unsigned long long a3 = pk2(a.w, a.w);
            fma2(acc[0][0], a0, p0); fma2(acc[0][1], a0, p1);
            fma2(acc[0][2], a0, p2); fma2(acc[0][3], a0, p3);
            fma2(acc[1][0], a1, p0); fma2(acc[1][1], a1, p1);
            fma2(acc[1][2], a1, p2); fma2(acc[1][3], a1, p3);
            fma2(acc[2][0], a2, p0); fma2(acc[2][1], a2, p1);
            fma2(acc[2][2], a2, p2); fma2(acc[2][3], a2, p3);
            fma2(acc[3][0], a3, p0); fma2(acc[3][1], a3, p1);
            fma2(acc[3][2], a3, p2); fma2(acc[3][3], a3, p3);
        }
        __syncthreads();
    }

    // epilogue: coalesced transposed stores (8 consecutive px per thread)
    float* outp = d_featp + (size_t)blockIdx.z * NO * NPIX;
#pragma unroll
    for (int c = 0; c < 4; c++) {
        int o = m0 + ty * 4 + c;
        if (o < NO) {
            float2 f0 = upk2(acc[c][0]);
            float2 f1 = upk2(acc[c][1]);
            float2 f2 = upk2(acc[c][2]);
            float2 f3 = upk2(acc[c][3]);
            float* dst = outp + (size_t)o * NPIX + pix0 + tx * 8;
            *(float4*)(dst + 0) = make_float4(f0.x, f0.y, f1.x, f1.y);
            *(float4*)(dst + 4) = make_float4(f2.x, f2.y, f3.x, f3.y);
        }
    }
}

// ---------------- softmax (thread-per-pixel) + bias + cfeat transpose ----------------
__global__ __launch_bounds__(128) void k_softmax(const float* __restrict__ bias) {
    int pix = blockIdx.x * 128 + threadIdx.x;
    const float* f0 = d_featp;
    const float* f1 = d_featp + NO * NPIX;

    // pass 1: max
    float m = -3.4e38f;
#pragma unroll 4
    for (int o = 0; o < DB; o++) {
        float v = f0[o * NPIX + pix] + f1[o * NPIX + pix] + bias[o];
        m = fmaxf(m, v);
    }
    // pass 2: exp + sum, stash unnormalized
    float s = 0.f;
    float* dep = d_dep + (size_t)pix * DB;
#pragma unroll 4
    for (int o = 0; o < DB; o++) {
        float v = f0[o * NPIX + pix] + f1[o * NPIX + pix] + bias[o];
        float e = __expf(v - m);
        s += e;
        dep[o] = e;
    }
    float inv = 1.0f / s;
#pragma unroll 4
    for (int o = 0; o < DB; o++) dep[o] *= inv;

    // cfeat: [pix][c] layout for the gather
    float* cf = d_cfeat + (size_t)pix * CT;
#pragma unroll 4
    for (int c = 0; c < CT; c++)
        cf[c] = f0[(DB + c) * NPIX + pix] + f1[(DB + c) * NPIX + pix] + bias[DB + c];
}

// ---------------- geometry -> voxel rank + histogram ----------------
__global__ void k_rank(const float* __restrict__ trans,
                       const float* __restrict__ post_trans) {
    int p = blockIdx.x * blockDim.x + threadIdx.x;
    if (p >= NPTS) return;
    int d   = p % DB;
    int pix = p / DB;
    int n   = pix / HW_;
    int hw  = pix % HW_;
    int h   = hw / FW_;
    int w   = hw % FW_;

    float xsv = (float)w * (703.0f / 43.0f);
    float ysv = (float)h * 17.0f;
    float dsv = 4.0f + (float)d;

    float px = xsv - post_trans[n * 3 + 0];
    float py = ysv - post_trans[n * 3 + 1];
    float pz = dsv - post_trans[n * 3 + 2];
    const float* IP = d_invpost + n * 9;
    float qx = IP[0]*px + IP[1]*py + IP[2]*pz;
    float qy = IP[3]*px + IP[4]*py + IP[5]*pz;
    float qz = IP[6]*px + IP[7]*py + IP[8]*pz;
    float rx = qx * qz, ry = qy * qz, rz = qz;
    const float* C = d_combine + n * 9;
    float gx = C[0]*rx + C[1]*ry + C[2]*rz + trans[n * 3 + 0];
    float gy = C[3]*rx + C[4]*ry + C[5]*rz + trans[n * 3 + 1];
    float gz = C[6]*rx + C[7]*ry + C[8]*rz + trans[n * 3 + 2];

    // truncation toward zero, matching jnp astype(int32)
    int ix = (int)((gx + 51.2f) / 0.8f);
    int iy = (int)((gy + 51.2f) / 0.8f);
    int iz = (int)((gz + 10.0f) / 20.0f);
    bool valid = (ix >= 0) & (ix < 128) & (iy >= 0) & (iy < 128) & (iz == 0);
    int r = valid ? (iy * 128 + ix) : NVOX;
    d_rank[p] = r;
    if (r < NVOX) atomicAdd(&d_cnt[r], 1);
}

// ---------------- exclusive scan of 16384 counts (1 block, 1024 thr) ----------------
__global__ void k_scan() {
    __shared__ int wsum[32];
    int t = threadIdx.x, lane = t & 31, wid = t >> 5;
    int base = t * 16;
    int s = 0;
#pragma unroll
    for (int k = 0; k < 16; k++) s += d_cnt[base + k];
    int val = s;
#pragma unroll
    for (int o = 1; o < 32; o <<= 1) {
        int u = __shfl_up_sync(0xffffffffu, val, o);
        if (lane >= o) val += u;
    }
    if (lane == 31) wsum[wid] = val;
    __syncthreads();
    if (wid == 0) {
        int wv = wsum[lane];
#pragma unroll
        for (int o = 1; o < 32; o <<= 1) {
            int u = __shfl_up_sync(0xffffffffu, wv, o);
            if (lane >= o) wv += u;
        }
        wsum[lane] = wv;
    }
    __syncthreads();
    int warpbase = (wid == 0) ? 0 : wsum[wid - 1];
    int run = warpbase + val - s;      // exclusive prefix for this thread's chunk
#pragma unroll
    for (int k = 0; k < 16; k++) {
        d_offs[base + k] = run;
        run += d_cnt[base + k];
    }
}

// ---------------- scatter points into bins ----------------
__global__ void k_scatter() {
    int p = blockIdx.x * blockDim.x + threadIdx.x;
    if (p >= NPTS) return;
    int r = d_rank[p];
    if (r < NVOX) {
        int pos = atomicAdd(&d_offs[r], 1);
        int pix = p / DB;
        d_sorted[pos] = make_int2(pix, __float_as_int(d_dep[p]));
    }
}

// ---------------- gather: 8 voxels per block, write final output directly ----------------
// after scatter: d_offs[v] == end of bin v; start = d_offs[v-1] (or 0)
__global__ __launch_bounds__(128) void k_gather(float* __restrict__ out) {
    int v0 = blockIdx.x * 8;
    int c  = threadIdx.x;                  // 128 channels
    float acc[8];
    int s = (v0 == 0) ? 0 : d_offs[v0 - 1];
#pragma unroll
    for (int j = 0; j < 8; j++) {
        int e = d_offs[v0 + j];
        float a = 0.f;
        for (int i = s; i < e; i++) {
            int2 pd = __ldg(&d_sorted[i]);
            a = fmaf(__int_as_float(pd.y), d_cfeat[(size_t)pd.x * CT + c], a);
        }
        acc[j] = a;
        s = e;
    }
    float* dst = out + (size_t)c * NVOX + v0;
    *(float4*)(dst + 0) = make_float4(acc[0], acc[1], acc[2], acc[3]);
    *(float4*)(dst + 4) = make_float4(acc[4], acc[5], acc[6], acc[7]);
}

// ---------------- launch ----------------
extern "C" void kernel_launch(void* const* d_in, const int* in_sizes, int n_in,
                              void* d_out, int out_size) {
    const float* x          = (const float*)d_in[0];
    const float* rots       = (const float*)d_in[1];
    const float* trans      = (const float*)d_in[2];
    const float* intrins    = (const float*)d_in[3];
    const float* post_rots  = (const float*)d_in[4];
    const float* post_trans = (const float*)d_in[5];
    const float* w_depth    = (const float*)d_in[6];
    const float* b_depth    = (const float*)d_in[7];
    float* out = (float*)d_out;

    k_init<<<65, 256>>>(rots, intrins, post_rots);
    k_gemm<<<dim3(NPIX / BN, 3, KSLICES), 128>>>(x, w_depth);
    k_softmax<<<NPIX / 128, 128>>>(b_depth);
    k_rank<<<(NPTS + 255) / 256, 256>>>(trans, post_trans);
    k_scan<<<1, 1024>>>();
    k_scatter<<<(NPTS + 255) / 256, 256>>>();
    k_gather<<<NVOX / 8, 128>>>(out);
}

// round 4
// speedup vs baseline: 1.0198x; 1.0198x over previous
#include <cuda_runtime.h>
#include <cuda_bf16.h>
#include <cstdint>

// ---------------- problem constants ----------------
#define FH_    16
#define FW_    44
#define HW_    704          // FH*FW
#define NCAM   6
#define CIN    512
#define DB     41           // depth bins
#define CT     128          // context channels
#define NO     169          // DB + CT
#define NOP    192          // padded NO for wT rows
#define NPIX   4224         // NCAM * HW_
#define NPTS   173184       // NPIX * DB
#define NVOX   16384        // 128*128

// GEMM tiling
#define BM 64               // output channels per block
#define BN 128              // pixels per block
#define BK 16
#define KSLICES 4
#define KSLICE (CIN / KSLICES)   // 128
#define NSTAGES (KSLICE / BK)    // 8

// ---------------- scratch (__device__ globals) ----------------
__device__ float d_invpost[NCAM * 9];
__device__ float d_combine[NCAM * 9];
__device__ float d_wT[CIN * NOP];                  // wT[c*NOP + o]
__device__ float d_featp[KSLICES * NO * NPIX];     // featT[ks][o][pix]
__device__ float d_dep[NPTS];                      // dep[pix*DB + d]
__device__ float d_cfeat[NPIX * CT];               // cfeat[pix*CT + c]
__device__ int   d_cnt[NVOX];
__device__ int   d_offs[NVOX];
__device__ int   d_rank[NPTS];
__device__ int2  d_sorted[NPTS];                   // (pix, depth-as-bits)

// ---------------- cp.async helpers ----------------
__device__ __forceinline__ void cp16(uint32_t dst, const void* src) {
    asm volatile("cp.async.cg.shared.global [%0], [%1], 16;\n" :: "r"(dst), "l"(src));
}
__device__ __forceinline__ void cp_commit() {
    asm volatile("cp.async.commit_group;\n" ::: "memory");
}
template <int N>
__device__ __forceinline__ void cp_wait() {
    asm volatile("cp.async.wait_group %0;\n" :: "n"(N) : "memory");
}

// ---------------- 3x3 inverse ----------------
__device__ __forceinline__ void inv3(const float* m, float* o) {
    float a=m[0],b=m[1],c=m[2],d=m[3],e=m[4],f=m[5],g=m[6],h=m[7],i=m[8];
    float A  =  (e*i - f*h);
    float Bc = -(d*i - f*g);
    float Cc =  (d*h - e*g);
    float det = a*A + b*Bc + c*Cc;
    float inv = 1.0f / det;
    o[0] = A  * inv;           o[1] = -(b*i - c*h) * inv;  o[2] =  (b*f - c*e) * inv;
    o[3] = Bc * inv;           o[4] =  (a*i - c*g) * inv;  o[5] = -(a*f - c*d) * inv;
    o[6] = Cc * inv;           o[7] = -(a*h - b*g) * inv;  o[8] =  (a*e - b*d) * inv;
}

// ---------------- K0: zero histogram + per-camera matrices ----------------
__global__ void k_init(const float* __restrict__ rots,
                       const float* __restrict__ intrins,
                       const float* __restrict__ post_rots) {
    int b = blockIdx.x;
    if (b < 64) {
        d_cnt[b * 256 + threadIdx.x] = 0;
    } else {
        int n = threadIdx.x;
        if (n >= NCAM) return;
        float ip[9], ii[9];
        inv3(post_rots + n * 9, ip);
        inv3(intrins  + n * 9, ii);
#pragma unroll
        for (int k = 0; k < 9; k++) d_invpost[n * 9 + k] = ip[k];
        const float* R = rots + n * 9;
#pragma unroll
        for (int i = 0; i < 3; i++)
#pragma unroll
            for (int j = 0; j < 3; j++) {
                float s = 0.f;
#pragma unroll
                for (int k = 0; k < 3; k++) s += R[i * 3 + k] * ii[k * 3 + j];
                d_combine[n * 9 + i * 3 + j] = s;
            }
    }
}

// ---------------- weight transpose with padding: wT[c][o] ----------------
__global__ void k_wt(const float* __restrict__ w) {
    int idx = blockIdx.x * blockDim.x + threadIdx.x;   // 512*192
    if (idx >= CIN * NOP) return;
    int c = idx / NOP, o = idx % NOP;
    d_wT[idx] = (o < NO) ? w[(size_t)o * CIN + c] : 0.f;
}

// ---------------- GEMM: featT[ks][o][pix], 8x8 thread tile, cp.async dbuf ----------------
__global__ __launch_bounds__(128) void k_gemm(const float* __restrict__ x) {
    __shared__ float ws[2][BK][BM];   // A: [k][m]
    __shared__ float xs[2][BK][BN];   // B: [k][n]

    int t    = threadIdx.x;
    int pix0 = blockIdx.x * BN;
    int m0   = blockIdx.y * BM;
    int k0   = blockIdx.z * KSLICE;

    // --- loader pointers (fixed col/row per thread, advance by k) ---
    // A: 64m x 16k = 256 float4 -> 2 per thread (buffer-0 smem offsets)
    const float* ag[2];
    uint32_t     as_off[2];
#pragma unroll
    for (int i = 0; i < 2; i++) {
        int idx  = t + i * 128;         // 0..255
        int arow = idx >> 4;            // k row 0..15
        int acol = (idx & 15) * 4;      // m col
        ag[i] = d_wT + (size_t)(k0 + arow) * NOP + m0 + acol;
        as_off[i] = (uint32_t)__cvta_generic_to_shared(&ws[0][arow][acol]);
    }
    // B: 16k x 128n = 512 float4 -> 4 per thread
    const float* bg[4];
    uint32_t     bs_off[4];
#pragma unroll
    for (int i = 0; i < 4; i++) {
        int idx  = t + i * 128;         // 0..511
        int brow = idx >> 5;            // k row 0..15
        int bcol = (idx & 31) * 4;      // n col
        int p    = pix0 + bcol;
        int cam  = p / HW_;
        int hw   = p - cam * HW_;
        bg[i] = x + ((size_t)cam * CIN + k0 + brow) * HW_ + hw;
        bs_off[i] = (uint32_t)__cvta_generic_to_shared(&xs[0][brow][bcol]);
    }
    const uint32_t WSB = (uint32_t)(BK * BM * 4);   // bytes per ws buffer
    const uint32_t XSB = (uint32_t)(BK * BN * 4);

    // prefetch stage 0 into buffer 0
#pragma unroll
    for (int i = 0; i < 2; i++) cp16(as_off[i], ag[i]);
#pragma unroll
    for (int i = 0; i < 4; i++) cp16(bs_off[i], bg[i]);
    cp_commit();

    int tm = (t >> 4) * 8;     // 8 output channels
    int tn = (t & 15) * 8;     // 8 pixels

    float acc[8][8];
#pragma unroll
    for (int j = 0; j < 8; j++)
#pragma unroll
        for (int i = 0; i < 8; i++) acc[j][i] = 0.f;

    for (int s = 0; s < NSTAGES; s++) {
        int buf = s & 1;
        if (s + 1 < NSTAGES) {
            uint32_t nboff = ((s + 1) & 1) ? 1u : 0u;   // next buffer index
#pragma unroll
            for (int i = 0; i < 2; i++)
                cp16(as_off[i] + nboff * WSB, ag[i] + (size_t)(s + 1) * BK * NOP);
#pragma unroll
            for (int i = 0; i < 4; i++)
                cp16(bs_off[i] + nboff * XSB, bg[i] + (size_t)(s + 1) * BK * HW_);
            cp_commit();
            cp_wait<1>();
        } else {
            cp_wait<0>();
        }
        __syncthreads();

#pragma unroll
        for (int kk = 0; kk < BK; kk++) {
            float4 a0 = *(const float4*)&ws[buf][kk][tm];
            float4 a1 = *(const float4*)&ws[buf][kk][tm + 4];
            float4 b0 = *(const float4*)&xs[buf][kk][tn];
            float4 b1 = *(const float4*)&xs[buf][kk][tn + 4];
            float a[8] = {a0.x, a0.y, a0.z, a0.w, a1.x, a1.y, a1.z, a1.w};
            float bb[8] = {b0.x, b0.y, b0.z, b0.w, b1.x, b1.y, b1.z, b1.w};
#pragma unroll
            for (int j = 0; j < 8; j++)
#pragma unroll
                for (int i = 0; i < 8; i++)
                    acc[j][i] = fmaf(a[j], bb[i], acc[j][i]);
        }
        __syncthreads();
    }

    // epilogue: coalesced stores, 8 px per thread per row
    float* outp = d_featp + (size_t)blockIdx.z * NO * NPIX;
#pragma unroll
    for (int j = 0; j < 8; j++) {
        int o = m0 + tm + j;
        if (o < NO) {
            float* dst = outp + (size_t)o * NPIX + pix0 + tn;
            *(float4*)(dst + 0) = make_float4(acc[j][0], acc[j][1], acc[j][2], acc[j][3]);
            *(float4*)(dst + 4) = make_float4(acc[j][4], acc[j][5], acc[j][6], acc[j][7]);
        }
    }
}

// ---------------- softmax (thread-per-pixel) + bias + cfeat transpose ----------------
__global__ __launch_bounds__(128) void k_softmax(const float* __restrict__ bias) {
    int pix = blockIdx.x * 128 + threadIdx.x;
    const float* f0 = d_featp;
    const float* f1 = d_featp + (size_t)NO * NPIX;
    const float* f2 = d_featp + (size_t)2 * NO * NPIX;
    const float* f3 = d_featp + (size_t)3 * NO * NPIX;

    float m = -3.4e38f;
#pragma unroll 4
    for (int o = 0; o < DB; o++) {
        size_t ix = (size_t)o * NPIX + pix;
        float v = f0[ix] + f1[ix] + f2[ix] + f3[ix] + bias[o];
        m = fmaxf(m, v);
    }
    float s = 0.f;
    float* dep = d_dep + (size_t)pix * DB;
#pragma unroll 4
    for (int o = 0; o < DB; o++) {
        size_t ix = (size_t)o * NPIX + pix;
        float v = f0[ix] + f1[ix] + f2[ix] + f3[ix] + bias[o];
        float e = __expf(v - m);
        s += e;
        dep[o] = e;
    }
    float inv = 1.0f / s;
#pragma unroll 4
    for (int o = 0; o < DB; o++) dep[o] *= inv;

    float* cf = d_cfeat + (size_t)pix * CT;
#pragma unroll 4
    for (int c = 0; c < CT; c++) {
        size_t ix = (size_t)(DB + c) * NPIX + pix;
        cf[c] = f0[ix] + f1[ix] + f2[ix] + f3[ix] + bias[DB + c];
    }
}

// ---------------- geometry -> voxel rank + histogram ----------------
__global__ void k_rank(const float* __restrict__ trans,
                       const float* __restrict__ post_trans) {
    int p = blockIdx.x * blockDim.x + threadIdx.x;
    if (p >= NPTS) return;
    int d   = p % DB;
    int pix = p / DB;
    int n   = pix / HW_;
    int hw  = pix % HW_;
    int h   = hw / FW_;
    int w   = hw % FW_;

    float xsv = (float)w * (703.0f / 43.0f);
    float ysv = (float)h * 17.0f;
    float dsv = 4.0f + (float)d;

    float px = xsv - post_trans[n * 3 + 0];
    float py = ysv - post_trans[n * 3 + 1];
    float pz = dsv - post_trans[n * 3 + 2];
    const float* IP = d_invpost + n * 9;
    float qx = IP[0]*px + IP[1]*py + IP[2]*pz;
    float qy = IP[3]*px + IP[4]*py + IP[5]*pz;
    float qz = IP[6]*px + IP[7]*py + IP[8]*pz;
    float rx = qx * qz, ry = qy * qz, rz = qz;
    const float* C = d_combine + n * 9;
    float gx = C[0]*rx + C[1]*ry + C[2]*rz + trans[n * 3 + 0];
    float gy = C[3]*rx + C[4]*ry + C[5]*rz + trans[n * 3 + 1];
    float gz = C[6]*rx + C[7]*ry + C[8]*rz + trans[n * 3 + 2];

    // truncation toward zero, matching jnp astype(int32)
    int ix = (int)((gx + 51.2f) / 0.8f);
    int iy = (int)((gy + 51.2f) / 0.8f);
    int iz = (int)((gz + 10.0f) / 20.0f);
    bool valid = (ix >= 0) & (ix < 128) & (iy >= 0) & (iy < 128) & (iz == 0);
    int r = valid ? (iy * 128 + ix) : NVOX;
    d_rank[p] = r;
    if (r < NVOX) atomicAdd(&d_cnt[r], 1);
}

// ---------------- exclusive scan of 16384 counts (1 block, 1024 thr) ----------------
__global__ void k_scan() {
    __shared__ int wsum[32];
    int t = threadIdx.x, lane = t & 31, wid = t >> 5;
    int base = t * 16;
    int s = 0;
#pragma unroll
    for (int k = 0; k < 16; k++) s += d_cnt[base + k];
    int val = s;
#pragma unroll
    for (int o = 1; o < 32; o <<= 1) {
        int u = __shfl_up_sync(0xffffffffu, val, o);
        if (lane >= o) val += u;
    }
    if (lane == 31) wsum[wid] = val;
    __syncthreads();
    if (wid == 0) {
        int wv = wsum[lane];
#pragma unroll
        for (int o = 1; o < 32; o <<= 1) {
            int u = __shfl_up_sync(0xffffffffu, wv, o);
            if (lane >= o) wv += u;
        }
        wsum[lane] = wv;
    }
    __syncthreads();
    int warpbase = (wid == 0) ? 0 : wsum[wid - 1];
    int run = warpbase + val - s;
#pragma unroll
    for (int k = 0; k < 16; k++) {
        d_offs[base + k] = run;
        run += d_cnt[base + k];
    }
}

// ---------------- scatter points into bins ----------------
__global__ void k_scatter() {
    int p = blockIdx.x * blockDim.x + threadIdx.x;
    if (p >= NPTS) return;
    int r = d_rank[p];
    if (r < NVOX) {
        int pos = atomicAdd(&d_offs[r], 1);
        int pix = p / DB;
        d_sorted[pos] = make_int2(pix, __float_as_int(d_dep[p]));
    }
}

// ---------------- gather: 8 voxels per block, write final output directly ----------------
__global__ __launch_bounds__(128) void k_gather(float* __restrict__ out) {
    int v0 = blockIdx.x * 8;
    int c  = threadIdx.x;                  // 128 channels
    float acc[8];
    int s = (v0 == 0) ? 0 : d_offs[v0 - 1];
#pragma unroll
    for (int j = 0; j < 8; j++) {
        int e = d_offs[v0 + j];
        float a = 0.f;
        for (int i = s; i < e; i++) {
            int2 pd = __ldg(&d_sorted[i]);
            a = fmaf(__int_as_float(pd.y), d_cfeat[(size_t)pd.x * CT + c], a);
        }
        acc[j] = a;
        s = e;
    }
    float* dst = out + (size_t)c * NVOX + v0;
    *(float4*)(dst + 0) = make_float4(acc[0], acc[1], acc[2], acc[3]);
    *(float4*)(dst + 4) = make_float4(acc[4], acc[5], acc[6], acc[7]);
}

// ---------------- launch ----------------
extern "C" void kernel_launch(void* const* d_in, const int* in_sizes, int n_in,
                              void* d_out, int out_size) {
    const float* x          = (const float*)d_in[0];
    const float* rots       = (const float*)d_in[1];
    const float* trans      = (const float*)d_in[2];
    const float* intrins    = (const float*)d_in[3];
    const float* post_rots  = (const float*)d_in[4];
    const float* post_trans = (const float*)d_in[5];
    const float* w_depth    = (const float*)d_in[6];
    const float* b_depth    = (const float*)d_in[7];
    float* out = (float*)d_out;

    k_init<<<65, 256>>>(rots, intrins, post_rots);
    k_wt<<<(CIN * NOP + 255) / 256, 256>>>(w_depth);
    k_gemm<<<dim3(NPIX / BN, 3, KSLICES), 128>>>(x);
    k_softmax<<<NPIX / 128, 128>>>(b_depth);
    k_rank<<<(NPTS + 255) / 256, 256>>>(trans, post_trans);
    k_scan<<<1, 1024>>>();
    k_scatter<<<(NPTS + 255) / 256, 256>>>();
    k_gather<<<NVOX / 8, 128>>>(out);
}

// round 5
// speedup vs baseline: 1.8048x; 1.7699x over previous
#include <cuda_runtime.h>
#include <cuda_bf16.h>
#include <cstdint>

// ---------------- problem constants ----------------
#define FH_    16
#define FW_    44
#define HW_    704          // FH*FW
#define NCAM   6
#define CIN    512
#define DB     41           // depth bins
#define CT     128          // context channels
#define NO     169          // DB + CT
#define NOP    192          // padded NO
#define NPIX   4224         // NCAM * HW_
#define NPTS   173184       // NPIX * DB
#define NVOX   16384        // 128*128
#define DSTR   48           // padded depth row stride

// GEMM tiling
#define BM 64               // output channels per block
#define BN 128              // pixels per block
#define BK 16
#define KSLICES 8
#define KSLICE (CIN / KSLICES)   // 64
#define NSTAGES (KSLICE / BK)    // 4

// ---------------- scratch (__device__ globals) ----------------
__device__ float d_invpost[NCAM * 9];
__device__ float d_combine[NCAM * 9];
__device__ float d_wT[CIN * NOP];                  // wT[c*NOP + o]
__device__ float d_featp[KSLICES * NO * NPIX];     // featT[ks][o][pix]
__device__ float d_depT[NPIX * DSTR];              // depth logits [pix][48]
__device__ float d_dep[NPTS];                      // dep[pix*DB + d]
__device__ float d_cfeat[NPIX * CT];               // cfeat[pix*CT + c]
__device__ int   d_cnt[NVOX];
__device__ int   d_offs[NVOX];
__device__ int   d_rank[NPTS];
__device__ int2  d_sorted[NPTS];                   // (pix, depth-as-bits)

// ---------------- cp.async helpers ----------------
__device__ __forceinline__ void cp16(uint32_t dst, const void* src) {
    asm volatile("cp.async.cg.shared.global [%0], [%1], 16;\n" :: "r"(dst), "l"(src));
}
__device__ __forceinline__ void cp_commit() {
    asm volatile("cp.async.commit_group;\n" ::: "memory");
}
template <int N>
__device__ __forceinline__ void cp_wait() {
    asm volatile("cp.async.wait_group %0;\n" :: "n"(N) : "memory");
}

// ---------------- 3x3 inverse ----------------
__device__ __forceinline__ void inv3(const float* m, float* o) {
    float a=m[0],b=m[1],c=m[2],d=m[3],e=m[4],f=m[5],g=m[6],h=m[7],i=m[8];
    float A  =  (e*i - f*h);
    float Bc = -(d*i - f*g);
    float Cc =  (d*h - e*g);
    float det = a*A + b*Bc + c*Cc;
    float inv = 1.0f / det;
    o[0] = A  * inv;           o[1] = -(b*i - c*h) * inv;  o[2] =  (b*f - c*e) * inv;
    o[3] = Bc * inv;           o[4] =  (a*i - c*g) * inv;  o[5] = -(a*f - c*d) * inv;
    o[6] = Cc * inv;           o[7] = -(a*h - b*g) * inv;  o[8] =  (a*e - b*d) * inv;
}

// ---------------- K0: zero histogram + per-camera matrices ----------------
__global__ void k_init(const float* __restrict__ rots,
                       const float* __restrict__ intrins,
                       const float* __restrict__ post_rots) {
    int b = blockIdx.x;
    if (b < 64) {
        d_cnt[b * 256 + threadIdx.x] = 0;
    } else {
        int n = threadIdx.x;
        if (n >= NCAM) return;
        float ip[9], ii[9];
        inv3(post_rots + n * 9, ip);
        inv3(intrins  + n * 9, ii);
#pragma unroll
        for (int k = 0; k < 9; k++) d_invpost[n * 9 + k] = ip[k];
        const float* R = rots + n * 9;
#pragma unroll
        for (int i = 0; i < 3; i++)
#pragma unroll
            for (int j = 0; j < 3; j++) {
                float s = 0.f;
#pragma unroll
                for (int k = 0; k < 3; k++) s += R[i * 3 + k] * ii[k * 3 + j];
                d_combine[n * 9 + i * 3 + j] = s;
            }
    }
}

// ---------------- weight transpose with padding: wT[c][o] ----------------
__global__ void k_wt(const float* __restrict__ w) {
    int idx = blockIdx.x * blockDim.x + threadIdx.x;   // 512*192
    if (idx >= CIN * NOP) return;
    int c = idx / NOP, o = idx % NOP;
    d_wT[idx] = (o < NO) ? w[(size_t)o * CIN + c] : 0.f;
}

// ---------------- GEMM: featT[ks][o][pix], 8x8 thread tile, cp.async dbuf ----------------
__global__ __launch_bounds__(128) void k_gemm(const float* __restrict__ x) {
    __shared__ float ws[2][BK][BM];   // A: [k][m]
    __shared__ float xs[2][BK][BN];   // B: [k][n]

    int t    = threadIdx.x;
    int pix0 = blockIdx.x * BN;
    int m0   = blockIdx.y * BM;
    int k0   = blockIdx.z * KSLICE;

    // A: 64m x 16k = 256 float4 -> 2 per thread
    const float* ag[2];
    uint32_t     as_off[2];
#pragma unroll
    for (int i = 0; i < 2; i++) {
        int idx  = t + i * 128;
        int arow = idx >> 4;
        int acol = (idx & 15) * 4;
        ag[i] = d_wT + (size_t)(k0 + arow) * NOP + m0 + acol;
        as_off[i] = (uint32_t)__cvta_generic_to_shared(&ws[0][arow][acol]);
    }
    // B: 16k x 128n = 512 float4 -> 4 per thread
    const float* bg[4];
    uint32_t     bs_off[4];
#pragma unroll
    for (int i = 0; i < 4; i++) {
        int idx  = t + i * 128;
        int brow = idx >> 5;
        int bcol = (idx & 31) * 4;
        int p    = pix0 + bcol;
        int cam  = p / HW_;
        int hw   = p - cam * HW_;
        bg[i] = x + ((size_t)cam * CIN + k0 + brow) * HW_ + hw;
        bs_off[i] = (uint32_t)__cvta_generic_to_shared(&xs[0][brow][bcol]);
    }
    const uint32_t WSB = (uint32_t)(BK * BM * 4);
    const uint32_t XSB = (uint32_t)(BK * BN * 4);

#pragma unroll
    for (int i = 0; i < 2; i++) cp16(as_off[i], ag[i]);
#pragma unroll
    for (int i = 0; i < 4; i++) cp16(bs_off[i], bg[i]);
    cp_commit();

    int tm = (t >> 4) * 8;
    int tn = (t & 15) * 8;

    float acc[8][8];
#pragma unroll
    for (int j = 0; j < 8; j++)
#pragma unroll
        for (int i = 0; i < 8; i++) acc[j][i] = 0.f;

    for (int s = 0; s < NSTAGES; s++) {
        int buf = s & 1;
        if (s + 1 < NSTAGES) {
            uint32_t nboff = ((s + 1) & 1) ? 1u : 0u;
#pragma unroll
            for (int i = 0; i < 2; i++)
                cp16(as_off[i] + nboff * WSB, ag[i] + (size_t)(s + 1) * BK * NOP);
#pragma unroll
            for (int i = 0; i < 4; i++)
                cp16(bs_off[i] + nboff * XSB, bg[i] + (size_t)(s + 1) * BK * HW_);
            cp_commit();
            cp_wait<1>();
        } else {
            cp_wait<0>();
        }
        __syncthreads();

#pragma unroll
        for (int kk = 0; kk < BK; kk++) {
            float4 a0 = *(const float4*)&ws[buf][kk][tm];
            float4 a1 = *(const float4*)&ws[buf][kk][tm + 4];
            float4 b0 = *(const float4*)&xs[buf][kk][tn];
            float4 b1 = *(const float4*)&xs[buf][kk][tn + 4];
            float a[8] = {a0.x, a0.y, a0.z, a0.w, a1.x, a1.y, a1.z, a1.w};
            float bb[8] = {b0.x, b0.y, b0.z, b0.w, b1.x, b1.y, b1.z, b1.w};
#pragma unroll
            for (int j = 0; j < 8; j++)
#pragma unroll
                for (int i = 0; i < 8; i++)
                    acc[j][i] = fmaf(a[j], bb[i], acc[j][i]);
        }
        __syncthreads();
    }

    float* outp = d_featp + (size_t)blockIdx.z * NO * NPIX;
#pragma unroll
    for (int j = 0; j < 8; j++) {
        int o = m0 + tm + j;
        if (o < NO) {
            float* dst = outp + (size_t)o * NPIX + pix0 + tn;
            *(float4*)(dst + 0) = make_float4(acc[j][0], acc[j][1], acc[j][2], acc[j][3]);
            *(float4*)(dst + 4) = make_float4(acc[j][4], acc[j][5], acc[j][6], acc[j][7]);
        }
    }
}

// ---------------- reduce K-slices + bias, transpose into [pix][o] layouts ----------------
// grid (NPIX/32, NOP/32), block (32,8). Writes d_depT (o<41) and d_cfeat (41<=o<169).
__global__ void k_reduce(const float* __restrict__ bias) {
    __shared__ float tile[32][33];
    int pix0 = blockIdx.x * 32;
    int o0   = blockIdx.y * 32;
    int tx = threadIdx.x, ty = threadIdx.y;

#pragma unroll
    for (int k = 0; k < 32; k += 8) {
        int o = o0 + ty + k;
        float v = 0.f;
        if (o < NO) {
            size_t ix = (size_t)o * NPIX + pix0 + tx;
#pragma unroll
            for (int s = 0; s < KSLICES; s++)
                v += d_featp[(size_t)s * NO * NPIX + ix];
            v += bias[o];
        }
        tile[ty + k][tx] = v;
    }
    __syncthreads();
    // write transposed: thread (tx->o, ty->pix)
#pragma unroll
    for (int k = 0; k < 32; k += 8) {
        int pix = pix0 + ty + k;
        int o   = o0 + tx;
        float v = tile[tx][ty + k];
        if (o < DB) {
            d_depT[(size_t)pix * DSTR + o] = v;
        } else if (o < NO) {
            d_cfeat[(size_t)pix * CT + (o - DB)] = v;
        }
    }
}

// ---------------- depth softmax: warp per pixel ----------------
__global__ __launch_bounds__(256) void k_softmax_dep() {
    int warp = (blockIdx.x * 256 + threadIdx.x) >> 5;    // 0..4223
    int lane = threadIdx.x & 31;
    if (warp >= NPIX) return;
    const float* row = d_depT + (size_t)warp * DSTR;
    float v0 = row[lane];                                // lane 0..31 < 41
    float v1 = (lane < 9) ? row[lane + 32] : -3.4e38f;
    float m = fmaxf(v0, v1);
#pragma unroll
    for (int o = 16; o; o >>= 1) m = fmaxf(m, __shfl_xor_sync(0xffffffffu, m, o));
    float e0 = __expf(v0 - m);
    float e1 = (lane < 9) ? __expf(v1 - m) : 0.f;
    float s = e0 + e1;
#pragma unroll
    for (int o = 16; o; o >>= 1) s += __shfl_xor_sync(0xffffffffu, s, o);
    float inv = 1.0f / s;
    float* dep = d_dep + (size_t)warp * DB;
    dep[lane] = e0 * inv;
    if (lane < 9) dep[lane + 32] = e1 * inv;
}

// ---------------- geometry -> voxel rank + histogram ----------------
__global__ void k_rank(const float* __restrict__ trans,
                       const float* __restrict__ post_trans) {
    int p = blockIdx.x * blockDim.x + threadIdx.x;
    if (p >= NPTS) return;
    int d   = p % DB;
    int pix = p / DB;
    int n   = pix / HW_;
    int hw  = pix % HW_;
    int h   = hw / FW_;
    int w   = hw % FW_;

    float xsv = (float)w * (703.0f / 43.0f);
    float ysv = (float)h * 17.0f;
    float dsv = 4.0f + (float)d;

    float px = xsv - post_trans[n * 3 + 0];
    float py = ysv - post_trans[n * 3 + 1];
    float pz = dsv - post_trans[n * 3 + 2];
    const float* IP = d_invpost + n * 9;
    float qx = IP[0]*px + IP[1]*py + IP[2]*pz;
    float qy = IP[3]*px + IP[4]*py + IP[5]*pz;
    float qz = IP[6]*px + IP[7]*py + IP[8]*pz;
    float rx = qx * qz, ry = qy * qz, rz = qz;
    const float* C = d_combine + n * 9;
    float gx = C[0]*rx + C[1]*ry + C[2]*rz + trans[n * 3 + 0];
    float gy = C[3]*rx + C[4]*ry + C[5]*rz + trans[n * 3 + 1];
    float gz = C[6]*rx + C[7]*ry + C[8]*rz + trans[n * 3 + 2];

    int ix = (int)((gx + 51.2f) / 0.8f);
    int iy = (int)((gy + 51.2f) / 0.8f);
    int iz = (int)((gz + 10.0f) / 20.0f);
    bool valid = (ix >= 0) & (ix < 128) & (iy >= 0) & (iy < 128) & (iz == 0);
    int r = valid ? (iy * 128 + ix) : NVOX;
    d_rank[p] = r;
    if (r < NVOX) atomicAdd(&d_cnt[r], 1);
}

// ---------------- exclusive scan of 16384 counts (1 block, 1024 thr) ----------------
__global__ void k_scan() {
    __shared__ int wsum[32];
    int t = threadIdx.x, lane = t & 31, wid = t >> 5;
    int base = t * 16;
    int s = 0;
#pragma unroll
    for (int k = 0; k < 16; k++) s += d_cnt[base + k];
    int val = s;
#pragma unroll
    for (int o = 1; o < 32; o <<= 1) {
        int u = __shfl_up_sync(0xffffffffu, val, o);
        if (lane >= o) val += u;
    }
    if (lane == 31) wsum[wid] = val;
    __syncthreads();
    if (wid == 0) {
        int wv = wsum[lane];
#pragma unroll
        for (int o = 1; o < 32; o <<= 1) {
            int u = __shfl_up_sync(0xffffffffu, wv, o);
            if (lane >= o) wv += u;
        }
        wsum[lane] = wv;
    }
    __syncthreads();
    int warpbase = (wid == 0) ? 0 : wsum[wid - 1];
    int run = warpbase + val - s;
#pragma unroll
    for (int k = 0; k < 16; k++) {
        d_offs[base + k] = run;
        run += d_cnt[base + k];
    }
}

// ---------------- scatter points into bins ----------------
__global__ void k_scatter() {
    int p = blockIdx.x * blockDim.x + threadIdx.x;
    if (p >= NPTS) return;
    int r = d_rank[p];
    if (r < NVOX) {
        int pos = atomicAdd(&d_offs[r], 1);
        int pix = p / DB;
        d_sorted[pos] = make_int2(pix, __float_as_int(d_dep[p]));
    }
}

// ---------------- gather: 4 voxels per block, write final output directly ----------------
__global__ __launch_bounds__(128) void k_gather(float* __restrict__ out) {
    int v0 = blockIdx.x * 4;
    int c  = threadIdx.x;                  // 128 channels
    float acc[4];
    int s = (v0 == 0) ? 0 : d_offs[v0 - 1];
#pragma unroll
    for (int j = 0; j < 4; j++) {
        int e = d_offs[v0 + j];
        float a = 0.f;
        for (int i = s; i < e; i++) {
            int2 pd = __ldg(&d_sorted[i]);
            a = fmaf(__int_as_float(pd.y), d_cfeat[(size_t)pd.x * CT + c], a);
        }
        acc[j] = a;
        s = e;
    }
    float* dst = out + (size_t)c * NVOX + v0;
    *(float4*)dst = make_float4(acc[0], acc[1], acc[2], acc[3]);
}

// ---------------- launch ----------------
extern "C" void kernel_launch(void* const* d_in, const int* in_sizes, int n_in,
                              void* d_out, int out_size) {
    const float* x          = (const float*)d_in[0];
    const float* rots       = (const float*)d_in[1];
    const float* trans      = (const float*)d_in[2];
    const float* intrins    = (const float*)d_in[3];
    const float* post_rots  = (const float*)d_in[4];
    const float* post_trans = (const float*)d_in[5];
    const float* w_depth    = (const float*)d_in[6];
    const float* b_depth    = (const float*)d_in[7];
    float* out = (float*)d_out;

    k_init<<<65, 256>>>(rots, intrins, post_rots);
    k_wt<<<(CIN * NOP + 255) / 256, 256>>>(w_depth);
    k_gemm<<<dim3(NPIX / BN, 3, KSLICES), 128>>>(x);
    k_reduce<<<dim3(NPIX / 32, NOP / 32), dim3(32, 8)>>>(b_depth);
    k_softmax_dep<<<(NPIX * 32 + 255) / 256, 256>>>();
    k_rank<<<(NPTS + 255) / 256, 256>>>(trans, post_trans);
    k_scan<<<1, 1024>>>();
    k_scatter<<<(NPTS + 255) / 256, 256>>>();
    k_gather<<<NVOX / 4, 128>>>(out);
}